// round 13
// baseline (speedup 1.0000x reference)
#include <cuda_runtime.h>
#include <cuda_fp16.h>
#include <stdint.h>
#include <math.h>

// Problem constants (fixed by the dataset)
#define BB 8
#define NV 500000
#define NF 1000000
#define VSTRIDE 32            // padded row: 24 used halfs + 8 pad = 64B (2 sectors)
#define NEPAD (6*NF + 8*NV)   // CSR capacity incl. per-vertex pad to multiple of 8

#define SCAN_CHUNK 1024
#define SCAN_NB ((NV + SCAN_CHUNK - 1)/SCAN_CHUNK)   // 489

// ---- device-global scratch (no cudaMalloc allowed) ----
// row NV is the dummy zero row (never written -> stays zero across replays)
__device__ __align__(128) __half g_vt[(size_t)(NV+1)*VSTRIDE];  // [N+1][32] fp16 (32 MB)
__device__ int   g_deg[NV];              // true degree
__device__ int   g_off[NV];              // CSR offsets of PADDED degrees (multiples of 8)
__device__ int   g_cur[NV];              // fill cursors
__device__ __align__(16) int g_adj[NEPAD];  // CSR adjacency (segment tails garbage, masked)
__device__ int   g_fi[3*NF];             // faces converted to clamped int32
__device__ int   g_bsum[1024];           // scan block sums
__device__ float g_ct[(size_t)NV*BB];    // curvature, vertex-major [N][8]
__device__ int   g_is64;                 // faces dtype flag (1 = int64, 0 = int32)

// ---------------------------------------------------------------------------
// 0) dtype probe: int64 faces with values < 500000 have all odd words zero.
// ---------------------------------------------------------------------------
__global__ void k_probe(const int* __restrict__ f) {
    __shared__ int any;
    if (threadIdx.x == 0) any = 0;
    __syncthreads();
    int bad = 0;
    for (int i = threadIdx.x; i < 4096; i += blockDim.x)
        if (f[2*i + 1] != 0) bad = 1;
    if (bad) atomicOr(&any, 1);
    __syncthreads();
    if (threadIdx.x == 0) g_is64 = (any == 0);
}

__device__ __forceinline__ void load_face_raw(const void* faces, int f,
                                              int& i, int& j, int& k) {
    if (g_is64) {
        const long long* p = (const long long*)faces + (size_t)f * 3;
        i = (int)p[0]; j = (int)p[1]; k = (int)p[2];
    } else {
        const int* p = (const int*)faces + (size_t)f * 3;
        i = p[0]; j = p[1]; k = p[2];
    }
    i = min(max(i, 0), NV - 1);
    j = min(max(j, 0), NV - 1);
    k = min(max(k, 0), NV - 1);
}

// ---------------------------------------------------------------------------
// 1) vert (B,N,3) -> vt (N, 32-padded) fp16: element b*3+c.
//    Fused: zero g_deg.
// ---------------------------------------------------------------------------
__global__ void k_transpose(const float* __restrict__ vert) {
    __shared__ float s[64*24];
    int n0 = blockIdx.x * 64;
    int t  = threadIdx.x;                 // 192 threads

    int gi = blockIdx.x * 192 + t;        // fused degree zeroing
    if (gi < NV) g_deg[gi] = 0;

    int nrem = NV - n0; if (nrem > 64) nrem = 64;
    int cnt = nrem * 3;
    #pragma unroll
    for (int b = 0; b < 8; b++) {
        if (t < cnt) {
            int v = t / 3, c = t - v*3;
            s[v*24 + b*3 + c] = vert[(size_t)b*NV*3 + (size_t)n0*3 + t];
        }
    }
    __syncthreads();
    int tot = nrem * 24;
    for (int i = t; i < tot; i += 192) {
        int v = i / 24, e = i - v*24;
        g_vt[(size_t)(n0 + v)*VSTRIDE + e] = __float2half(s[i]);
    }
}

// ---------------------------------------------------------------------------
// 3) degree histogram + int32 face conversion (single faces pass)
// ---------------------------------------------------------------------------
__global__ void k_hist(const void* __restrict__ faces) {
    int f = blockIdx.x * blockDim.x + threadIdx.x;
    if (f >= NF) return;
    int i, j, k;
    load_face_raw(faces, f, i, j, k);
    size_t o = (size_t)f * 3;
    g_fi[o] = i; g_fi[o+1] = j; g_fi[o+2] = k;
    atomicAdd(&g_deg[i], 2);
    atomicAdd(&g_deg[j], 2);
    atomicAdd(&g_deg[k], 2);
}

// ---------------------------------------------------------------------------
// 4a) per-block sums of PADDED degrees ((deg+7)&~7)
// ---------------------------------------------------------------------------
__device__ __forceinline__ int pdeg_of(int i) {
    return (i < NV) ? ((g_deg[i] + 7) & ~7) : 0;
}

__global__ void k_scanA() {
    __shared__ int s[SCAN_CHUNK];
    int i = blockIdx.x * SCAN_CHUNK + threadIdx.x;
    s[threadIdx.x] = pdeg_of(i);
    __syncthreads();
    for (int d = SCAN_CHUNK/2; d > 0; d >>= 1) {
        if (threadIdx.x < d) s[threadIdx.x] += s[threadIdx.x + d];
        __syncthreads();
    }
    if (threadIdx.x == 0) g_bsum[blockIdx.x] = s[0];
}

// ---------------------------------------------------------------------------
// 4b) final offsets: each block masked-reduces the preceding block sums,
//     then local exclusive scan. Writes offsets + fill cursors. No pad
//     writes (gather masks the tail). (R7-measured scan fold.)
// ---------------------------------------------------------------------------
__global__ void k_scanC() {
    __shared__ int r[SCAN_CHUNK];
    __shared__ int s[SCAN_CHUNK];
    int t = threadIdx.x;

    r[t] = (t < blockIdx.x && t < SCAN_NB) ? g_bsum[t] : 0;
    __syncthreads();
    for (int d = SCAN_CHUNK/2; d > 0; d >>= 1) {
        if (t < d) r[t] += r[t + d];
        __syncthreads();
    }
    int bpref = r[0];

    int i = blockIdx.x * SCAN_CHUNK + t;
    int pd = pdeg_of(i);
    s[t] = pd;
    __syncthreads();
    for (int d = 1; d < SCAN_CHUNK; d <<= 1) {
        int x = (t >= d) ? s[t-d] : 0;
        __syncthreads();
        s[t] += x;
        __syncthreads();
    }
    int ex = s[t] - pd + bpref;
    if (i < NV) { g_off[i] = ex; g_cur[i] = ex; }
}

// ---------------------------------------------------------------------------
// 5) CSR fill: per face, append the 2 neighbors of each corner (int2 stores)
// ---------------------------------------------------------------------------
__global__ void k_fill() {
    int f = blockIdx.x * blockDim.x + threadIdx.x;
    if (f >= NF) return;
    size_t o = (size_t)f * 3;
    int i = g_fi[o], j = g_fi[o+1], k = g_fi[o+2];
    int p;
    p = atomicAdd(&g_cur[i], 2); *(int2*)&g_adj[p] = make_int2(j, k);
    p = atomicAdd(&g_cur[j], 2); *(int2*)&g_adj[p] = make_int2(i, k);
    p = atomicAdd(&g_cur[k], 2); *(int2*)&g_adj[p] = make_int2(i, j);
}

// ---------------------------------------------------------------------------
// 6) gather + curvature: one warp per vertex, lane e<24 owns element b*3+c.
//    fp16 rows (64B): each neighbor visit = 2 sectors from L2-resident vt.
//    Main loop identical to R10/R12; final partial 8-group masked to the
//    L1-hot dummy zero row NV (replaces scanC's pad writes).
// ---------------------------------------------------------------------------
__global__ void k_gather() {
    int gw   = (blockIdx.x * blockDim.x + threadIdx.x) >> 5;
    int lane = threadIdx.x & 31;
    if (gw >= NV) return;

    int start = g_off[gw];
    int deg   = g_deg[gw];
    int fend  = start + (deg & ~7);       // full 8-groups
    int end   = start + deg;

    bool act = lane < 24;
    float own = 0.f, acc = 0.f;
    if (act) own = __half2float(__ldg(&g_vt[(size_t)gw*VSTRIDE + lane]));

    int base = start;
    for (; base < fend; base += 8) {
        int4 q0 = __ldg((const int4*)&g_adj[base]);
        int4 q1 = __ldg((const int4*)&g_adj[base + 4]);
        if (act) {
            float a = __half2float(__ldg(&g_vt[(size_t)q0.x*VSTRIDE + lane]));
            float b = __half2float(__ldg(&g_vt[(size_t)q0.y*VSTRIDE + lane]));
            float c = __half2float(__ldg(&g_vt[(size_t)q0.z*VSTRIDE + lane]));
            float d = __half2float(__ldg(&g_vt[(size_t)q0.w*VSTRIDE + lane]));
            float e = __half2float(__ldg(&g_vt[(size_t)q1.x*VSTRIDE + lane]));
            float f = __half2float(__ldg(&g_vt[(size_t)q1.y*VSTRIDE + lane]));
            float g = __half2float(__ldg(&g_vt[(size_t)q1.z*VSTRIDE + lane]));
            float h = __half2float(__ldg(&g_vt[(size_t)q1.w*VSTRIDE + lane]));
            acc += ((a + b) + (c + d)) + ((e + f) + (g + h));
        }
    }
    if (base < end) {                      // masked tail (deg%8 in {2,4,6})
        int4 q0 = __ldg((const int4*)&g_adj[base]);
        int4 q1 = __ldg((const int4*)&g_adj[base + 4]);
        int i0 = (base + 0 < end) ? q0.x : NV;
        int i1 = (base + 1 < end) ? q0.y : NV;
        int i2 = (base + 2 < end) ? q0.z : NV;
        int i3 = (base + 3 < end) ? q0.w : NV;
        int i4 = (base + 4 < end) ? q1.x : NV;
        int i5 = (base + 5 < end) ? q1.y : NV;
        int i6 = (base + 6 < end) ? q1.z : NV;
        if (act) {
            float a = __half2float(__ldg(&g_vt[(size_t)i0*VSTRIDE + lane]));
            float b = __half2float(__ldg(&g_vt[(size_t)i1*VSTRIDE + lane]));
            float c = __half2float(__ldg(&g_vt[(size_t)i2*VSTRIDE + lane]));
            float d = __half2float(__ldg(&g_vt[(size_t)i3*VSTRIDE + lane]));
            float e = __half2float(__ldg(&g_vt[(size_t)i4*VSTRIDE + lane]));
            float f = __half2float(__ldg(&g_vt[(size_t)i5*VSTRIDE + lane]));
            float g = __half2float(__ldg(&g_vt[(size_t)i6*VSTRIDE + lane]));
            acc += ((a + b) + (c + d)) + ((e + f) + g);
        }
    }

    float inv = 1.f / fmaxf((float)deg, 1.f);
    float lap = acc * inv - own;
    float sq  = lap * lap;
    float s1 = __shfl_down_sync(0xffffffffu, sq, 1);
    float s2 = __shfl_down_sync(0xffffffffu, sq, 2);
    float sum = sq + s1 + s2;
    if (act && (lane % 3) == 0)
        g_ct[(size_t)gw*8 + lane/3] = sqrtf(sum);
}

// ---------------------------------------------------------------------------
// 7) output transpose: g_ct [N][8] -> out [8][N]
// ---------------------------------------------------------------------------
__global__ void k_outT(float* __restrict__ out) {
    __shared__ float s[32*9];             // pad 8->9 to kill bank conflicts
    int n0 = blockIdx.x * 32;
    int t  = threadIdx.x;                 // 256 threads
    {
        int v = t >> 3, e = t & 7;
        s[v*9 + e] = g_ct[(size_t)n0*8 + t];   // coalesced 1KB read
    }
    __syncthreads();
    int b = t >> 5, v = t & 31;
    out[(size_t)b*NV + n0 + v] = s[v*9 + b];   // coalesced 128B per batch row
}

// ---------------------------------------------------------------------------
extern "C" void kernel_launch(void* const* d_in, const int* in_sizes, int n_in,
                              void* d_out, int out_size) {
    const float* vert  = (const float*)d_in[0];   // (8, 500000, 3) f32
    const void*  faces = d_in[1];                 // (1000000, 3) i64 OR i32
    float* out = (float*)d_out;                   // (8, 500000) f32

    // 0) detect faces dtype
    k_probe<<<1, 256>>>((const int*)faces);
    // 1) transpose vertices into padded fp16 [N][32] (+ fused degree zeroing)
    k_transpose<<<(NV + 63) / 64, 192>>>(vert);
    // 3) degree histogram + int32 conversion
    k_hist<<<(NF + 255) / 256, 256>>>(faces);
    // 4) scan of padded degrees -> aligned CSR offsets (2 kernels, folded)
    k_scanA<<<SCAN_NB, SCAN_CHUNK>>>();
    k_scanC<<<SCAN_NB, SCAN_CHUNK>>>();
    // 5) CSR fill (int32 faces, int2 stores)
    k_fill<<<(NF + 255) / 256, 256>>>();
    // 6) gather + curvature (warp per vertex, int4 adj, masked tail)
    k_gather<<<(NV * 32) / 256, 256>>>();
    // 7) output transpose
    k_outT<<<NV / 32, 256>>>(out);
}

// round 14
// speedup vs baseline: 1.0277x; 1.0277x over previous
#include <cuda_runtime.h>
#include <cuda_fp16.h>
#include <stdint.h>
#include <math.h>

// Problem constants (fixed by the dataset)
#define BB 8
#define NV 500000
#define NF 1000000
#define VSTRIDE 32            // padded row: 24 used halfs + 8 pad = 64B (2 sectors)
#define NEPAD (6*NF + 8*NV)   // CSR capacity incl. per-vertex pad to multiple of 8

#define SCAN_CHUNK 1024
#define SCAN_NB ((NV + SCAN_CHUNK - 1)/SCAN_CHUNK)   // 489

// ---- device-global scratch (no cudaMalloc allowed) ----
// row NV is the dummy zero row (never written -> stays zero across replays)
__device__ __align__(128) __half g_vt[(size_t)(NV+1)*VSTRIDE];  // [N+1][32] fp16 (32 MB)
__device__ int   g_deg[NV];              // true degree
__device__ int   g_off[NV];              // CSR offsets of PADDED degrees (multiples of 8)
__device__ int   g_cur[NV];              // fill cursors
__device__ __align__(16) int g_adj[NEPAD];  // CSR adjacency (segment tails garbage, masked)
__device__ int   g_fi[3*NF];             // faces converted to clamped int32
__device__ int   g_bsum[1024];           // scan block sums
__device__ float g_ct[(size_t)NV*BB];    // curvature, vertex-major [N][8]
__device__ int   g_is64;                 // faces dtype flag (1 = int64, 0 = int32)

// ---------------------------------------------------------------------------
// 0) dtype probe: int64 faces with values < 500000 have all odd words zero.
// ---------------------------------------------------------------------------
__global__ void k_probe(const int* __restrict__ f) {
    __shared__ int any;
    if (threadIdx.x == 0) any = 0;
    __syncthreads();
    int bad = 0;
    for (int i = threadIdx.x; i < 4096; i += blockDim.x)
        if (f[2*i + 1] != 0) bad = 1;
    if (bad) atomicOr(&any, 1);
    __syncthreads();
    if (threadIdx.x == 0) g_is64 = (any == 0);
}

__device__ __forceinline__ void load_face_raw(const void* faces, int f,
                                              int& i, int& j, int& k) {
    if (g_is64) {
        const long long* p = (const long long*)faces + (size_t)f * 3;
        i = (int)p[0]; j = (int)p[1]; k = (int)p[2];
    } else {
        const int* p = (const int*)faces + (size_t)f * 3;
        i = p[0]; j = p[1]; k = p[2];
    }
    i = min(max(i, 0), NV - 1);
    j = min(max(j, 0), NV - 1);
    k = min(max(k, 0), NV - 1);
}

// ---------------------------------------------------------------------------
// 1) vert (B,N,3) -> vt (N, 32-padded) fp16: element b*3+c.
//    Fused: zero g_deg.
// ---------------------------------------------------------------------------
__global__ void k_transpose(const float* __restrict__ vert) {
    __shared__ float s[64*24];
    int n0 = blockIdx.x * 64;
    int t  = threadIdx.x;                 // 192 threads

    int gi = blockIdx.x * 192 + t;        // fused degree zeroing
    if (gi < NV) g_deg[gi] = 0;

    int nrem = NV - n0; if (nrem > 64) nrem = 64;
    int cnt = nrem * 3;
    #pragma unroll
    for (int b = 0; b < 8; b++) {
        if (t < cnt) {
            int v = t / 3, c = t - v*3;
            s[v*24 + b*3 + c] = vert[(size_t)b*NV*3 + (size_t)n0*3 + t];
        }
    }
    __syncthreads();
    int tot = nrem * 24;
    for (int i = t; i < tot; i += 192) {
        int v = i / 24, e = i - v*24;
        g_vt[(size_t)(n0 + v)*VSTRIDE + e] = __float2half(s[i]);
    }
}

// ---------------------------------------------------------------------------
// 3) degree histogram + int32 face conversion (single faces pass)
// ---------------------------------------------------------------------------
__global__ void k_hist(const void* __restrict__ faces) {
    int f = blockIdx.x * blockDim.x + threadIdx.x;
    if (f >= NF) return;
    int i, j, k;
    load_face_raw(faces, f, i, j, k);
    size_t o = (size_t)f * 3;
    g_fi[o] = i; g_fi[o+1] = j; g_fi[o+2] = k;
    atomicAdd(&g_deg[i], 2);
    atomicAdd(&g_deg[j], 2);
    atomicAdd(&g_deg[k], 2);
}

// ---------------------------------------------------------------------------
// 4a) per-block sums of PADDED degrees ((deg+7)&~7) — warp-shuffle reduce,
//     single __syncthreads.
// ---------------------------------------------------------------------------
__device__ __forceinline__ int pdeg_of(int i) {
    return (i < NV) ? ((g_deg[i] + 7) & ~7) : 0;
}

__global__ void k_scanA() {
    __shared__ int ws[32];
    int t    = threadIdx.x;               // 1024 threads
    int lane = t & 31;
    int warp = t >> 5;
    int v = pdeg_of(blockIdx.x * SCAN_CHUNK + t);
    #pragma unroll
    for (int d = 16; d > 0; d >>= 1)
        v += __shfl_down_sync(0xffffffffu, v, d);
    if (lane == 0) ws[warp] = v;
    __syncthreads();
    if (warp == 0) {
        int x = ws[lane];
        #pragma unroll
        for (int d = 16; d > 0; d >>= 1)
            x += __shfl_down_sync(0xffffffffu, x, d);
        if (lane == 0) g_bsum[blockIdx.x] = x;
    }
}

// ---------------------------------------------------------------------------
// 4b) final offsets — warp-shuffle scan (4 syncs total):
//     bpref  = masked warp-reduce over preceding block sums
//     local  = per-warp inclusive shfl scan + warp-total scan by warp 0
// ---------------------------------------------------------------------------
__global__ void k_scanC() {
    __shared__ int rs[32];                // partial sums for block prefix
    __shared__ int ws[32];                // warp totals for local scan
    __shared__ int sh_bpref;
    int t    = threadIdx.x;               // 1024 threads
    int lane = t & 31;
    int warp = t >> 5;

    // ---- block prefix: sum g_bsum[k] for k < blockIdx.x ----
    int r = (t < blockIdx.x && t < SCAN_NB) ? g_bsum[t] : 0;
    #pragma unroll
    for (int d = 16; d > 0; d >>= 1)
        r += __shfl_down_sync(0xffffffffu, r, d);
    if (lane == 0) rs[warp] = r;

    // ---- local inclusive scan of pdeg within the warp ----
    int i  = blockIdx.x * SCAN_CHUNK + t;
    int pd = pdeg_of(i);
    int x  = pd;
    #pragma unroll
    for (int d = 1; d < 32; d <<= 1) {
        int y = __shfl_up_sync(0xffffffffu, x, d);
        if (lane >= d) x += y;
    }
    if (lane == 31) ws[warp] = x;
    __syncthreads();

    if (warp == 0) {
        // finish block prefix
        int rr = rs[lane];
        #pragma unroll
        for (int d = 16; d > 0; d >>= 1)
            rr += __shfl_down_sync(0xffffffffu, rr, d);
        if (lane == 0) sh_bpref = rr;
        // exclusive scan of 32 warp totals
        int w = ws[lane];
        int xs = w;
        #pragma unroll
        for (int d = 1; d < 32; d <<= 1) {
            int y = __shfl_up_sync(0xffffffffu, xs, d);
            if (lane >= d) xs += y;
        }
        ws[lane] = xs - w;                // exclusive warp offset
    }
    __syncthreads();

    int ex = (x - pd) + ws[warp] + sh_bpref;
    if (i < NV) { g_off[i] = ex; g_cur[i] = ex; }
}

// ---------------------------------------------------------------------------
// 5) CSR fill: per face, append the 2 neighbors of each corner (int2 stores)
// ---------------------------------------------------------------------------
__global__ void k_fill() {
    int f = blockIdx.x * blockDim.x + threadIdx.x;
    if (f >= NF) return;
    size_t o = (size_t)f * 3;
    int i = g_fi[o], j = g_fi[o+1], k = g_fi[o+2];
    int p;
    p = atomicAdd(&g_cur[i], 2); *(int2*)&g_adj[p] = make_int2(j, k);
    p = atomicAdd(&g_cur[j], 2); *(int2*)&g_adj[p] = make_int2(i, k);
    p = atomicAdd(&g_cur[k], 2); *(int2*)&g_adj[p] = make_int2(i, j);
}

// ---------------------------------------------------------------------------
// 6) gather + curvature: one warp per vertex, lane e<24 owns element b*3+c.
//    fp16 rows (64B): each neighbor visit = 2 sectors from L2-resident vt.
//    Main loop identical to R10/R12; final partial 8-group masked to the
//    L1-hot dummy zero row NV.
// ---------------------------------------------------------------------------
__global__ void k_gather() {
    int gw   = (blockIdx.x * blockDim.x + threadIdx.x) >> 5;
    int lane = threadIdx.x & 31;
    if (gw >= NV) return;

    int start = g_off[gw];
    int deg   = g_deg[gw];
    int fend  = start + (deg & ~7);       // full 8-groups
    int end   = start + deg;

    bool act = lane < 24;
    float own = 0.f, acc = 0.f;
    if (act) own = __half2float(__ldg(&g_vt[(size_t)gw*VSTRIDE + lane]));

    int base = start;
    for (; base < fend; base += 8) {
        int4 q0 = __ldg((const int4*)&g_adj[base]);
        int4 q1 = __ldg((const int4*)&g_adj[base + 4]);
        if (act) {
            float a = __half2float(__ldg(&g_vt[(size_t)q0.x*VSTRIDE + lane]));
            float b = __half2float(__ldg(&g_vt[(size_t)q0.y*VSTRIDE + lane]));
            float c = __half2float(__ldg(&g_vt[(size_t)q0.z*VSTRIDE + lane]));
            float d = __half2float(__ldg(&g_vt[(size_t)q0.w*VSTRIDE + lane]));
            float e = __half2float(__ldg(&g_vt[(size_t)q1.x*VSTRIDE + lane]));
            float f = __half2float(__ldg(&g_vt[(size_t)q1.y*VSTRIDE + lane]));
            float g = __half2float(__ldg(&g_vt[(size_t)q1.z*VSTRIDE + lane]));
            float h = __half2float(__ldg(&g_vt[(size_t)q1.w*VSTRIDE + lane]));
            acc += ((a + b) + (c + d)) + ((e + f) + (g + h));
        }
    }
    if (base < end) {                      // masked tail (deg%8 in {2,4,6})
        int4 q0 = __ldg((const int4*)&g_adj[base]);
        int4 q1 = __ldg((const int4*)&g_adj[base + 4]);
        int i0 = (base + 0 < end) ? q0.x : NV;
        int i1 = (base + 1 < end) ? q0.y : NV;
        int i2 = (base + 2 < end) ? q0.z : NV;
        int i3 = (base + 3 < end) ? q0.w : NV;
        int i4 = (base + 4 < end) ? q1.x : NV;
        int i5 = (base + 5 < end) ? q1.y : NV;
        int i6 = (base + 6 < end) ? q1.z : NV;
        if (act) {
            float a = __half2float(__ldg(&g_vt[(size_t)i0*VSTRIDE + lane]));
            float b = __half2float(__ldg(&g_vt[(size_t)i1*VSTRIDE + lane]));
            float c = __half2float(__ldg(&g_vt[(size_t)i2*VSTRIDE + lane]));
            float d = __half2float(__ldg(&g_vt[(size_t)i3*VSTRIDE + lane]));
            float e = __half2float(__ldg(&g_vt[(size_t)i4*VSTRIDE + lane]));
            float f = __half2float(__ldg(&g_vt[(size_t)i5*VSTRIDE + lane]));
            float g = __half2float(__ldg(&g_vt[(size_t)i6*VSTRIDE + lane]));
            acc += ((a + b) + (c + d)) + ((e + f) + g);
        }
    }

    float inv = 1.f / fmaxf((float)deg, 1.f);
    float lap = acc * inv - own;
    float sq  = lap * lap;
    float s1 = __shfl_down_sync(0xffffffffu, sq, 1);
    float s2 = __shfl_down_sync(0xffffffffu, sq, 2);
    float sum = sq + s1 + s2;
    if (act && (lane % 3) == 0)
        g_ct[(size_t)gw*8 + lane/3] = sqrtf(sum);
}

// ---------------------------------------------------------------------------
// 7) output transpose: g_ct [N][8] -> out [8][N]
// ---------------------------------------------------------------------------
__global__ void k_outT(float* __restrict__ out) {
    __shared__ float s[32*9];             // pad 8->9 to kill bank conflicts
    int n0 = blockIdx.x * 32;
    int t  = threadIdx.x;                 // 256 threads
    {
        int v = t >> 3, e = t & 7;
        s[v*9 + e] = g_ct[(size_t)n0*8 + t];   // coalesced 1KB read
    }
    __syncthreads();
    int b = t >> 5, v = t & 31;
    out[(size_t)b*NV + n0 + v] = s[v*9 + b];   // coalesced 128B per batch row
}

// ---------------------------------------------------------------------------
extern "C" void kernel_launch(void* const* d_in, const int* in_sizes, int n_in,
                              void* d_out, int out_size) {
    const float* vert  = (const float*)d_in[0];   // (8, 500000, 3) f32
    const void*  faces = d_in[1];                 // (1000000, 3) i64 OR i32
    float* out = (float*)d_out;                   // (8, 500000) f32

    // 0) detect faces dtype
    k_probe<<<1, 256>>>((const int*)faces);
    // 1) transpose vertices into padded fp16 [N][32] (+ fused degree zeroing)
    k_transpose<<<(NV + 63) / 64, 192>>>(vert);
    // 3) degree histogram + int32 conversion
    k_hist<<<(NF + 255) / 256, 256>>>(faces);
    // 4) scan of padded degrees -> aligned CSR offsets (warp-shuffle scans)
    k_scanA<<<SCAN_NB, SCAN_CHUNK>>>();
    k_scanC<<<SCAN_NB, SCAN_CHUNK>>>();
    // 5) CSR fill (int32 faces, int2 stores)
    k_fill<<<(NF + 255) / 256, 256>>>();
    // 6) gather + curvature (warp per vertex, int4 adj, masked tail)
    k_gather<<<(NV * 32) / 256, 256>>>();
    // 7) output transpose
    k_outT<<<NV / 32, 256>>>(out);
}